// round 1
// baseline (speedup 1.0000x reference)
#include <cuda_runtime.h>
#include <cstdint>

// LoRIExpertBank as a single NT GEMM:
//   out[t,d] = sum_c Q[t,c] * Aflat[d,c],  c = k*64 + r,  Q[t,c] = w[t,k]*p[t,r]
// T=16384, D=4096, C=512. SCALING = 64/64 = 1.0. A is pre-masked in setup, so
// sparse_mask is a bitwise no-op and is ignored. tf32 mma.sync, fp32 accumulate.

#define BM 128
#define BN 128
#define BK 16
#define KC 512
#define TOK 16384
#define DIM 4096
#define NIT (KC / BK)   // 32

__device__ __forceinline__ uint32_t f2tf32(float x) {
    uint32_t u;
    asm("cvt.rna.tf32.f32 %0, %1;" : "=r"(u) : "f"(x));
    return u;
}

__device__ __forceinline__ void mma_tf32(float c[4],
                                         uint32_t a0, uint32_t a1, uint32_t a2, uint32_t a3,
                                         uint32_t b0, uint32_t b1) {
    asm volatile(
        "mma.sync.aligned.m16n8k8.row.col.f32.tf32.tf32.f32 "
        "{%0,%1,%2,%3}, {%4,%5,%6,%7}, {%8,%9}, {%0,%1,%2,%3};"
        : "+f"(c[0]), "+f"(c[1]), "+f"(c[2]), "+f"(c[3])
        : "r"(a0), "r"(a1), "r"(a2), "r"(a3), "r"(b0), "r"(b1));
}

// smem layout per tile: [row][16] floats (64B rows).
// k-permutation: k = j*8 + c, c = tg + 4h  ->  pos = tg*4 + j*2 + h
//   (so each thread's whole BK=16 fragment is one contiguous float4)
// XOR swizzle: float-pos ^= ((row>>1)&3)*4  -> conflict-free LDS.128 and STS.32.

__global__ __launch_bounds__(256, 1)
void lori_gemm_tf32(const float* __restrict__ P,   // [TOK, 64]
                    const float* __restrict__ W,   // [TOK, 8]
                    const float* __restrict__ A,   // [8, 4096, 64]
                    float* __restrict__ OUT)       // [TOK, 4096]
{
    __shared__ float Qs[2][BM * BK];
    __shared__ float As[2][BN * BK];

    const int tid  = threadIdx.x;
    const int lane = tid & 31;
    const int warp = tid >> 5;
    const int g    = lane >> 2;   // 0..7
    const int tg   = lane & 3;    // 0..3
    const int wm   = warp >> 1;   // 0..3  (M band of 32)
    const int wn   = warp & 1;    // 0..1  (N band of 64)
    const int mBase = blockIdx.y * BM;
    const int nBase = blockIdx.x * BN;
    const int lrow = tid >> 2;    // 0..63 (load row)
    const int lm4  = tid & 3;     // which float4 within a 16-float row

    float acc[2][8][4];
    #pragma unroll
    for (int mi = 0; mi < 2; ++mi)
        #pragma unroll
        for (int ni = 0; ni < 8; ++ni)
            #pragma unroll
            for (int e = 0; e < 4; ++e) acc[mi][ni][e] = 0.0f;

    float4 qv[2];  // raw p float4 per staged row
    float  wv[2];  // routing weight per staged row
    float4 av[2];  // raw A float4 per staged row

    auto load_iter = [&](int kb) {
        const int ke = kb >> 2;              // expert index
        const int r0 = (kb & 3) * BK;        // rank offset within expert
        #pragma unroll
        for (int rr = 0; rr < 2; ++rr) {
            const int row = lrow + rr * 64;
            const int t   = mBase + row;
            qv[rr] = *reinterpret_cast<const float4*>(P + (size_t)t * 64 + r0 + lm4 * 4);
            wv[rr] = W[t * 8 + ke];
            const int d = nBase + row;
            av[rr] = *reinterpret_cast<const float4*>(
                A + (size_t)ke * (DIM * 64) + (size_t)d * 64 + r0 + lm4 * 4);
        }
    };

    auto sts_iter = [&](int b) {
        #pragma unroll
        for (int rr = 0; rr < 2; ++rr) {
            const int row = lrow + rr * 64;
            const int s   = ((row >> 1) & 3) * 4;
            float* q = &Qs[b][row * BK];
            float* a = &As[b][row * BK];
            float qx[4] = { qv[rr].x * wv[rr], qv[rr].y * wv[rr],
                            qv[rr].z * wv[rr], qv[rr].w * wv[rr] };
            float ax[4] = { av[rr].x, av[rr].y, av[rr].z, av[rr].w };
            #pragma unroll
            for (int i = 0; i < 4; ++i) {
                const int pos = (i * 4 + lm4) ^ s;   // k-perm: global k = lm4*4 + i
                q[pos] = __uint_as_float(f2tf32(qx[i]));
                a[pos] = __uint_as_float(f2tf32(ax[i]));
            }
        }
    };

    auto compute = [&](int b) {
        // A fragments: 2 mtiles x 2 rows, each a single LDS.128
        uint32_t aq[2][2][4];
        #pragma unroll
        for (int mi = 0; mi < 2; ++mi)
            #pragma unroll
            for (int rr = 0; rr < 2; ++rr) {
                const int arow = wm * 32 + mi * 16 + rr * 8 + g;
                const int s    = ((arow >> 1) & 3) * 4;
                float4 v = *reinterpret_cast<const float4*>(
                    &Qs[b][arow * BK + ((tg * 4) ^ s)]);
                aq[mi][rr][0] = __float_as_uint(v.x);
                aq[mi][rr][1] = __float_as_uint(v.y);
                aq[mi][rr][2] = __float_as_uint(v.z);
                aq[mi][rr][3] = __float_as_uint(v.w);
            }
        #pragma unroll
        for (int ni = 0; ni < 8; ++ni) {
            const int brow = wn * 64 + ni * 8 + g;
            const int s    = ((brow >> 1) & 3) * 4;
            float4 v = *reinterpret_cast<const float4*>(
                &As[b][brow * BK + ((tg * 4) ^ s)]);
            const uint32_t b0 = __float_as_uint(v.x);
            const uint32_t b1 = __float_as_uint(v.y);
            const uint32_t b2 = __float_as_uint(v.z);
            const uint32_t b3 = __float_as_uint(v.w);
            #pragma unroll
            for (int mi = 0; mi < 2; ++mi) {
                // kstep 0: quad elements {x=(k0,tg), y=(k0,tg+4)}
                mma_tf32(acc[mi][ni],
                         aq[mi][0][0], aq[mi][1][0], aq[mi][0][1], aq[mi][1][1],
                         b0, b1);
                // kstep 1: quad elements {z=(k1,tg), w=(k1,tg+4)}
                mma_tf32(acc[mi][ni],
                         aq[mi][0][2], aq[mi][1][2], aq[mi][0][3], aq[mi][1][3],
                         b2, b3);
            }
        }
    };

    // Pipeline: double-buffered smem, global loads for it+1 issued before compute(it)
    load_iter(0);
    sts_iter(0);
    __syncthreads();

    #pragma unroll 1
    for (int it = 0; it < NIT; ++it) {
        const int b = it & 1;
        if (it + 1 < NIT) load_iter(it + 1);
        compute(b);
        if (it + 1 < NIT) sts_iter(1 - b);
        __syncthreads();
    }

    // Epilogue: c0,c1 -> (row g, cols 2tg,2tg+1); c2,c3 -> row g+8. float2 stores,
    // each 8-lane g-group covers one full 32B sector.
    #pragma unroll
    for (int mi = 0; mi < 2; ++mi)
        #pragma unroll
        for (int rr = 0; rr < 2; ++rr) {
            const int row = mBase + wm * 32 + mi * 16 + rr * 8 + g;
            float* o = OUT + (size_t)row * DIM + nBase + wn * 64 + tg * 2;
            #pragma unroll
            for (int ni = 0; ni < 8; ++ni) {
                float2 v = make_float2(acc[mi][ni][rr * 2], acc[mi][ni][rr * 2 + 1]);
                *reinterpret_cast<float2*>(o + ni * 8) = v;
            }
        }
}

extern "C" void kernel_launch(void* const* d_in, const int* in_sizes, int n_in,
                              void* d_out, int out_size) {
    const float* P = (const float*)d_in[0];  // projected_input [4,4096,64]
    const float* W = (const float*)d_in[1];  // routing_weights [4,4096,8]
    const float* A = (const float*)d_in[2];  // A [8,4096,64] (pre-masked)
    // d_in[3] (sparse_mask) intentionally unused: A = A*mask already in setup,
    // and mask is binary so re-masking is an exact no-op.
    (void)in_sizes; (void)n_in; (void)out_size;
    float* OUT = (float*)d_out;

    dim3 grid(DIM / BN, TOK / BM);   // (32, 128); x-fastest keeps A + Q band in L2
    lori_gemm_tf32<<<grid, 256>>>(P, W, A, OUT);
}